// round 4
// baseline (speedup 1.0000x reference)
#include <cuda_runtime.h>
#include <cuda_fp16.h>
#include <cstdint>

#define NSTEPS   64
#define NTHREADS 256
#define NTILES   1024            // 262144 rows / 256 per CTA (M=32 per warp)

// SMEM: W1 [256n][64k] half, rows padded to 144B; W2 [64n][256k] half, rows 528B
//       b1 f32[256]; y state: per-thread 64 f32, rows padded to 272B
#define OFF_W1 0u                // 36864
#define OFF_W2 36864u            // 33792
#define OFF_B1 70656u            // 1024
#define OFF_Y  71680u            // 256*272 = 69632
#define YPITCH 272u
#define SMEM_BYTES (OFF_Y + 256u * YPITCH)   // 141312

static __device__ __forceinline__ uint32_t smem_u32(const void* p) {
    uint32_t a;
    asm("{ .reg .u64 t; cvta.to.shared.u64 t, %1; cvt.u32.u64 %0, t; }" : "=r"(a) : "l"(p));
    return a;
}
static __device__ __forceinline__ void ldsm4(uint32_t* r, uint32_t addr) {
    asm volatile("ldmatrix.sync.aligned.m8n8.x4.shared.b16 {%0,%1,%2,%3}, [%4];"
                 : "=r"(r[0]), "=r"(r[1]), "=r"(r[2]), "=r"(r[3]) : "r"(addr));
}
static __device__ __forceinline__ void mma16816(float* d, const uint32_t* a,
                                                uint32_t b0, uint32_t b1) {
    asm volatile(
        "mma.sync.aligned.m16n8k16.row.col.f32.f16.f16.f32 "
        "{%0,%1,%2,%3}, {%4,%5,%6,%7}, {%8,%9}, {%0,%1,%2,%3};"
        : "+f"(d[0]), "+f"(d[1]), "+f"(d[2]), "+f"(d[3])
        : "r"(a[0]), "r"(a[1]), "r"(a[2]), "r"(a[3]), "r"(b0), "r"(b1));
}
static __device__ __forceinline__ uint32_t pack_h2(float a, float b) {
    __half2 h = __floats2half2_rn(a, b);
    return *reinterpret_cast<const uint32_t*>(&h);
}
static __device__ __forceinline__ __half2 exp2h2(__half2 v) {
    uint32_t r, x = *reinterpret_cast<const uint32_t*>(&v);
    asm("ex2.approx.f16x2 %0, %1;" : "=r"(r) : "r"(x));
    return *reinterpret_cast<const __half2*>(&r);
}
// branchless fp16x2 ELU: max(x,0) + (exp(min(x,0)) - 1)
static __device__ __forceinline__ uint32_t elu2(float v0, float v1) {
    const __half2 z    = __float2half2_rn(0.0f);
    const __half2 l2e  = __float2half2_rn(1.44269504f);
    const __half2 one  = __float2half2_rn(1.0f);
    __half2 h  = __floats2half2_rn(v0, v1);
    __half2 mn = __hmin2(h, z);
    __half2 mx = __hmax2(h, z);
    __half2 e  = exp2h2(__hmul2(mn, l2e));
    __half2 r  = __hadd2(mx, __hsub2(e, one));
    return *reinterpret_cast<const uint32_t*>(&r);
}

__global__ void __launch_bounds__(NTHREADS, 1)
node_rk4_kernel(const float* __restrict__ x, const float* __restrict__ tptr,
                const float* __restrict__ W1, const float* __restrict__ b1,
                const float* __restrict__ W2, const float* __restrict__ b2,
                float* __restrict__ out)
{
    extern __shared__ char base[];
    const int tid = threadIdx.x;
    const int wid = tid >> 5;
    const int lid = tid & 31;
    const int g   = lid >> 2;
    const int tig = lid & 3;

    // ---- stage weights (fp16, padded rows) + b1 ----
    for (int i = tid; i < 256 * 64; i += NTHREADS) {
        int n = i >> 6, k = i & 63;
        *reinterpret_cast<__half*>(base + OFF_W1 + n * 144 + k * 2) = __float2half_rn(W1[i]);
    }
    for (int i = tid; i < 64 * 256; i += NTHREADS) {
        int n = i >> 8, k = i & 255;
        *reinterpret_cast<__half*>(base + OFF_W2 + n * 528 + k * 2) = __float2half_rn(W2[i]);
    }
    for (int i = tid; i < 256; i += NTHREADS)
        reinterpret_cast<float*>(base + OFF_B1)[i] = b1[i];

    const uint32_t sb = smem_u32(base);
    const uint32_t lr = lid & 7, lh = (lid >> 3) & 1, ln = (lid >> 4) & 1;
    const uint32_t w1base = sb + OFF_W1 + (lr + 8 * ln) * 144 + lh * 16;
    const uint32_t w2base = sb + OFF_W2 + (lr + 8 * ln) * 528 + lh * 16;
    const float2* b1p = reinterpret_cast<const float2*>(base + OFF_B1);
    float* yp = reinterpret_cast<float*>(base + OFF_Y + (uint32_t)tid * YPITCH);

    float b2f[16];
    #pragma unroll
    for (int t = 0; t < 8; t++) {
        float2 v = *reinterpret_cast<const float2*>(b2 + 8 * t + tig * 2);
        b2f[2*t] = v.x; b2f[2*t+1] = v.y;
    }

    const float t0f = tptr[0];
    const float dt  = t0f * (1.0f / (float)NSTEPS);
    const float dt6 = dt * (1.0f / 6.0f);
    const float hdt = 0.5f * dt;
    const int   rot = wid & 3;             // per-warp chunk phase stagger

    // ---- initial y: gather C-layout slices from global x ----
    const int rowbase = blockIdx.x * 256 + wid * 32 + g;
    uint32_t a1[32];                       // A-frags of GEMM1, 2 rowsets x 16
    {
        float yl[64];
        #pragma unroll
        for (int rs = 0; rs < 2; rs++)
            #pragma unroll
            for (int h = 0; h < 2; h++) {
                const float2* src = reinterpret_cast<const float2*>(
                    x + (size_t)(rowbase + rs * 16 + h * 8) * 64);
                #pragma unroll
                for (int t = 0; t < 8; t++) {
                    float2 v = src[4 * t + tig];
                    yl[rs*32 + 4*t + 2*h]     = v.x;
                    yl[rs*32 + 4*t + 2*h + 1] = v.y;
                }
            }
        #pragma unroll
        for (int q = 0; q < 16; q++)
            reinterpret_cast<float4*>(yp)[q] =
                make_float4(yl[4*q], yl[4*q+1], yl[4*q+2], yl[4*q+3]);
        #pragma unroll
        for (int rs = 0; rs < 2; rs++)
            #pragma unroll
            for (int j = 0; j < 16; j++)
                a1[rs*16 + j] = pack_h2(yl[rs*32 + 2*j], yl[rs*32 + 2*j + 1]);
    }
    __syncthreads();

    // ---- main ODE loop ----
    #pragma unroll 1
    for (int step = 0; step < NSTEPS; ++step) {
        __half2 acc[32];
        #pragma unroll
        for (int i = 0; i < 32; i++) acc[i] = __float2half2_rn(0.0f);

        #pragma unroll 1
        for (int s = 0; s < 4; s++) {
            float d2[64];
            #pragma unroll
            for (int rs = 0; rs < 2; rs++)
                #pragma unroll
                for (int t = 0; t < 8; t++) {
                    d2[rs*32 + 4*t + 0] = b2f[2*t];
                    d2[rs*32 + 4*t + 1] = b2f[2*t+1];
                    d2[rs*32 + 4*t + 2] = b2f[2*t];
                    d2[rs*32 + 4*t + 3] = b2f[2*t+1];
                }

            float    d1c[64];
            uint32_t a2c[32];
            int cprev = 0;

            // Software pipeline over hidden chunks (order rotated per warp):
            //   it=0:        GEMM1(c0); ELU(c0)
            //   it=1..3:     GEMM1(ci) interleaved with GEMM2(c_{i-1}); ELU(ci)
            //   epilogue:    GEMM2(c3)
            #pragma unroll 1
            for (int it = 0; it < 4; ++it) {
                const int ci = (it + rot) & 3;

                // d1c init = b1 chunk ci
                #pragma unroll
                for (int ngl = 0; ngl < 4; ngl++) {
                    int tb = 8 * ci + 2 * ngl;
                    float2 bA = b1p[4*tb + tig];
                    float2 bB = b1p[4*tb + 4 + tig];
                    #pragma unroll
                    for (int rs = 0; rs < 2; rs++) {
                        d1c[rs*32 + 8*ngl + 0] = bA.x; d1c[rs*32 + 8*ngl + 1] = bA.y;
                        d1c[rs*32 + 8*ngl + 2] = bA.x; d1c[rs*32 + 8*ngl + 3] = bA.y;
                        d1c[rs*32 + 8*ngl + 4] = bB.x; d1c[rs*32 + 8*ngl + 5] = bB.y;
                        d1c[rs*32 + 8*ngl + 6] = bB.x; d1c[rs*32 + 8*ngl + 7] = bB.y;
                    }
                }

                if (it == 0) {
                    // prologue: GEMM1 only
                    #pragma unroll
                    for (int j = 0; j < 16; j++) {
                        const int ngl = j >> 2, kk = j & 3;
                        uint32_t bb[4];
                        ldsm4(bb, w1base + (uint32_t)(4*ci + ngl) * 2304 + kk * 32);
                        mma16816(d1c + 8*ngl,          a1 + 4*kk,      bb[0], bb[1]);
                        mma16816(d1c + 8*ngl + 4,      a1 + 4*kk,      bb[2], bb[3]);
                        mma16816(d1c + 32 + 8*ngl,     a1 + 16 + 4*kk, bb[0], bb[1]);
                        mma16816(d1c + 32 + 8*ngl + 4, a1 + 16 + 4*kk, bb[2], bb[3]);
                    }
                } else {
                    // steady state: GEMM1(ci) + GEMM2(cprev), interleaved
                    #pragma unroll
                    for (int j = 0; j < 16; j++) {
                        const int ngl = j >> 2, kk = j & 3;   // GEMM1 roles
                        const int ng2 = j >> 2, kk2 = j & 3;  // GEMM2 roles
                        uint32_t bb1[4], bb2[4];
                        ldsm4(bb1, w1base + (uint32_t)(4*ci + ngl) * 2304 + kk * 32);
                        mma16816(d1c + 8*ngl,          a1 + 4*kk,      bb1[0], bb1[1]);
                        mma16816(d1c + 8*ngl + 4,      a1 + 4*kk,      bb1[2], bb1[3]);
                        mma16816(d1c + 32 + 8*ngl,     a1 + 16 + 4*kk, bb1[0], bb1[1]);
                        mma16816(d1c + 32 + 8*ngl + 4, a1 + 16 + 4*kk, bb1[2], bb1[3]);
                        ldsm4(bb2, w2base + (uint32_t)ng2 * 8448 + (uint32_t)(4*cprev + kk2) * 32);
                        mma16816(d2 + 8*ng2,          a2c + 4*kk2,      bb2[0], bb2[1]);
                        mma16816(d2 + 8*ng2 + 4,      a2c + 4*kk2,      bb2[2], bb2[3]);
                        mma16816(d2 + 32 + 8*ng2,     a2c + 16 + 4*kk2, bb2[0], bb2[1]);
                        mma16816(d2 + 32 + 8*ng2 + 4, a2c + 16 + 4*kk2, bb2[2], bb2[3]);
                    }
                }

                // ELU(ci) -> a2c
                #pragma unroll
                for (int rs = 0; rs < 2; rs++)
                    #pragma unroll
                    for (int p = 0; p < 16; p++)
                        a2c[rs*16 + p] = elu2(d1c[rs*32 + 2*p], d1c[rs*32 + 2*p + 1]);
                cprev = ci;
            }

            // epilogue: GEMM2 of last chunk
            #pragma unroll
            for (int j = 0; j < 16; j++) {
                const int ng2 = j >> 2, kk2 = j & 3;
                uint32_t bb[4];
                ldsm4(bb, w2base + (uint32_t)ng2 * 8448 + (uint32_t)(4*cprev + kk2) * 32);
                mma16816(d2 + 8*ng2,          a2c + 4*kk2,      bb[0], bb[1]);
                mma16816(d2 + 8*ng2 + 4,      a2c + 4*kk2,      bb[2], bb[3]);
                mma16816(d2 + 32 + 8*ng2,     a2c + 16 + 4*kk2, bb[0], bb[1]);
                mma16816(d2 + 32 + 8*ng2 + 4, a2c + 16 + 4*kk2, bb[2], bb[3]);
            }

            // ---- RK4 stage update ----
            const __half2 wh = __float2half2_rn((s == 1 || s == 2) ? 2.0f : 1.0f);
            #pragma unroll
            for (int i = 0; i < 32; i++) {
                __half2 pk = __floats2half2_rn(d2[2*i], d2[2*i+1]);
                acc[i] = __hfma2(pk, wh, acc[i]);
            }
            float yl[64];
            #pragma unroll
            for (int q = 0; q < 16; q++) {
                float4 v = reinterpret_cast<const float4*>(yp)[q];
                yl[4*q] = v.x; yl[4*q+1] = v.y; yl[4*q+2] = v.z; yl[4*q+3] = v.w;
            }
            if (s < 3) {
                const float cn = (s < 2) ? hdt : dt;
                #pragma unroll
                for (int rs = 0; rs < 2; rs++)
                    #pragma unroll
                    for (int j = 0; j < 16; j++)
                        a1[rs*16 + j] = pack_h2(yl[rs*32 + 2*j]     + cn * d2[rs*32 + 2*j],
                                                yl[rs*32 + 2*j + 1] + cn * d2[rs*32 + 2*j + 1]);
            } else {
                #pragma unroll
                for (int i = 0; i < 32; i++) {
                    float2 af = __half22float2(acc[i]);
                    yl[2*i]     += dt6 * af.x;
                    yl[2*i + 1] += dt6 * af.y;
                }
                #pragma unroll
                for (int q = 0; q < 16; q++)
                    reinterpret_cast<float4*>(yp)[q] =
                        make_float4(yl[4*q], yl[4*q+1], yl[4*q+2], yl[4*q+3]);
                #pragma unroll
                for (int rs = 0; rs < 2; rs++)
                    #pragma unroll
                    for (int j = 0; j < 16; j++)
                        a1[rs*16 + j] = pack_h2(yl[rs*32 + 2*j], yl[rs*32 + 2*j + 1]);
            }
        }
    }

    // ---- output ----
    {
        float yl[64];
        #pragma unroll
        for (int q = 0; q < 16; q++) {
            float4 v = reinterpret_cast<const float4*>(yp)[q];
            yl[4*q] = v.x; yl[4*q+1] = v.y; yl[4*q+2] = v.z; yl[4*q+3] = v.w;
        }
        #pragma unroll
        for (int rs = 0; rs < 2; rs++)
            #pragma unroll
            for (int h = 0; h < 2; h++) {
                float2* dst = reinterpret_cast<float2*>(
                    out + (size_t)(rowbase + rs * 16 + h * 8) * 64);
                #pragma unroll
                for (int t = 0; t < 8; t++)
                    dst[4 * t + tig] = make_float2(yl[rs*32 + 4*t + 2*h],
                                                   yl[rs*32 + 4*t + 2*h + 1]);
            }
    }
}

extern "C" void kernel_launch(void* const* d_in, const int* in_sizes, int n_in,
                              void* d_out, int out_size) {
    const float* x  = (const float*)d_in[0];
    const float* t  = (const float*)d_in[1];
    const float* W1 = (const float*)d_in[2];
    const float* b1 = (const float*)d_in[3];
    const float* W2 = (const float*)d_in[4];
    const float* b2 = (const float*)d_in[5];
    float* out = (float*)d_out;

    cudaFuncSetAttribute(node_rk4_kernel,
                         cudaFuncAttributeMaxDynamicSharedMemorySize, SMEM_BYTES);
    node_rk4_kernel<<<NTILES, NTHREADS, SMEM_BYTES>>>(x, t, W1, b1, W2, b2, out);
}

// round 5
// speedup vs baseline: 1.0486x; 1.0486x over previous
#include <cuda_runtime.h>
#include <cuda_fp16.h>
#include <cstdint>

#define NSTEPS   64
#define NTHREADS 256
#define NTILES   1024            // 262144 rows / 256 per CTA (M=32 per warp)

// SMEM: W1 [256n][64k] half, rows padded to 144B; W2 [64n][256k] half, rows 528B
//       b1 f32[256]; y state: per-thread 64 f32, rows padded to 272B
#define OFF_W1 0u                // 36864
#define OFF_W2 36864u            // 33792
#define OFF_B1 70656u            // 1024
#define OFF_Y  71680u            // 256*272 = 69632
#define YPITCH 272u
#define SMEM_BYTES (OFF_Y + 256u * YPITCH)   // 141312

static __device__ __forceinline__ uint32_t smem_u32(const void* p) {
    uint32_t a;
    asm("{ .reg .u64 t; cvta.to.shared.u64 t, %1; cvt.u32.u64 %0, t; }" : "=r"(a) : "l"(p));
    return a;
}
static __device__ __forceinline__ void ldsm4(uint32_t* r, uint32_t addr) {
    asm volatile("ldmatrix.sync.aligned.m8n8.x4.shared.b16 {%0,%1,%2,%3}, [%4];"
                 : "=r"(r[0]), "=r"(r[1]), "=r"(r[2]), "=r"(r[3]) : "r"(addr));
}
static __device__ __forceinline__ void mma16816(float* d, const uint32_t* a,
                                                uint32_t b0, uint32_t b1) {
    asm volatile(
        "mma.sync.aligned.m16n8k16.row.col.f32.f16.f16.f32 "
        "{%0,%1,%2,%3}, {%4,%5,%6,%7}, {%8,%9}, {%0,%1,%2,%3};"
        : "+f"(d[0]), "+f"(d[1]), "+f"(d[2]), "+f"(d[3])
        : "r"(a[0]), "r"(a[1]), "r"(a[2]), "r"(a[3]), "r"(b0), "r"(b1));
}
static __device__ __forceinline__ uint32_t pack_h2(float a, float b) {
    __half2 h = __floats2half2_rn(a, b);
    return *reinterpret_cast<const uint32_t*>(&h);
}
static __device__ __forceinline__ __half2 exp2h2(__half2 v) {
    uint32_t r, x = *reinterpret_cast<const uint32_t*>(&v);
    asm("ex2.approx.f16x2 %0, %1;" : "=r"(r) : "r"(x));
    return *reinterpret_cast<const __half2*>(&r);
}
// branchless fp16x2 ELU: max(x,0) + (exp(min(x,0)) - 1)
static __device__ __forceinline__ uint32_t elu2(float v0, float v1) {
    const __half2 z    = __float2half2_rn(0.0f);
    const __half2 l2e  = __float2half2_rn(1.44269504f);
    const __half2 one  = __float2half2_rn(1.0f);
    __half2 h  = __floats2half2_rn(v0, v1);
    __half2 mn = __hmin2(h, z);
    __half2 mx = __hmax2(h, z);
    __half2 e  = exp2h2(__hmul2(mn, l2e));
    __half2 r  = __hadd2(mx, __hsub2(e, one));
    return *reinterpret_cast<const uint32_t*>(&r);
}

__global__ void __launch_bounds__(NTHREADS, 1)
node_rk4_kernel(const float* __restrict__ x, const float* __restrict__ tptr,
                const float* __restrict__ W1, const float* __restrict__ b1,
                const float* __restrict__ W2, const float* __restrict__ b2,
                float* __restrict__ out)
{
    extern __shared__ char base[];
    const int tid = threadIdx.x;
    const int wid = tid >> 5;
    const int lid = tid & 31;
    const int g   = lid >> 2;
    const int tig = lid & 3;

    // ---- stage weights (fp16, padded rows) + b1 ----
    for (int i = tid; i < 256 * 64; i += NTHREADS) {
        int n = i >> 6, k = i & 63;
        *reinterpret_cast<__half*>(base + OFF_W1 + n * 144 + k * 2) = __float2half_rn(W1[i]);
    }
    for (int i = tid; i < 64 * 256; i += NTHREADS) {
        int n = i >> 8, k = i & 255;
        *reinterpret_cast<__half*>(base + OFF_W2 + n * 528 + k * 2) = __float2half_rn(W2[i]);
    }
    for (int i = tid; i < 256; i += NTHREADS)
        reinterpret_cast<float*>(base + OFF_B1)[i] = b1[i];

    const uint32_t sb = smem_u32(base);
    const uint32_t lr = lid & 7, lh = (lid >> 3) & 1, ln = (lid >> 4) & 1;
    const uint32_t w1base = sb + OFF_W1 + (lr + 8 * ln) * 144 + lh * 16;
    const uint32_t w2base = sb + OFF_W2 + (lr + 8 * ln) * 528 + lh * 16;
    const float2* b1p = reinterpret_cast<const float2*>(base + OFF_B1);
    float* yp = reinterpret_cast<float*>(base + OFF_Y + (uint32_t)tid * YPITCH);

    float b2f[16];
    #pragma unroll
    for (int t = 0; t < 8; t++) {
        float2 v = *reinterpret_cast<const float2*>(b2 + 8 * t + tig * 2);
        b2f[2*t] = v.x; b2f[2*t+1] = v.y;
    }

    const float t0f = tptr[0];
    const float dt  = t0f * (1.0f / (float)NSTEPS);
    const float dt6 = dt * (1.0f / 6.0f);
    const float hdt = 0.5f * dt;
    // SMSP-level phase stagger: warps w and w+4 share a scheduler; offset their
    // chunk order by 2 so epilogue bubbles of one overlap GEMM bursts of the other.
    const int rot = ((wid >> 2) & 1) * 2;

    // ---- initial y: gather C-layout slices from global x ----
    const int rowbase = blockIdx.x * 256 + wid * 32 + g;
    uint32_t a1[32];                      // A-frags of GEMM1, 2 rowsets x 16
    {
        float yl[64];
        #pragma unroll
        for (int rs = 0; rs < 2; rs++)
            #pragma unroll
            for (int h = 0; h < 2; h++) {
                const float2* src = reinterpret_cast<const float2*>(
                    x + (size_t)(rowbase + rs * 16 + h * 8) * 64);
                #pragma unroll
                for (int t = 0; t < 8; t++) {
                    float2 v = src[4 * t + tig];
                    yl[rs*32 + 4*t + 2*h]     = v.x;
                    yl[rs*32 + 4*t + 2*h + 1] = v.y;
                }
            }
        #pragma unroll
        for (int q = 0; q < 16; q++)
            reinterpret_cast<float4*>(yp)[q] =
                make_float4(yl[4*q], yl[4*q+1], yl[4*q+2], yl[4*q+3]);
        #pragma unroll
        for (int rs = 0; rs < 2; rs++)
            #pragma unroll
            for (int j = 0; j < 16; j++)
                a1[rs*16 + j] = pack_h2(yl[rs*32 + 2*j], yl[rs*32 + 2*j + 1]);
    }
    __syncthreads();

    // ---- main ODE loop ----
    #pragma unroll 1
    for (int step = 0; step < NSTEPS; ++step) {
        __half2 acc[32];                    // RK4 accumulator (fp16x2)
        #pragma unroll
        for (int i = 0; i < 32; i++) acc[i] = __float2half2_rn(0.0f);

        #pragma unroll 1
        for (int s = 0; s < 4; s++) {
            // D2 accumulators (both rowsets), init = b2
            float d2[64];
            #pragma unroll
            for (int rs = 0; rs < 2; rs++)
                #pragma unroll
                for (int t = 0; t < 8; t++) {
                    d2[rs*32 + 4*t + 0] = b2f[2*t];
                    d2[rs*32 + 4*t + 1] = b2f[2*t+1];
                    d2[rs*32 + 4*t + 2] = b2f[2*t];
                    d2[rs*32 + 4*t + 3] = b2f[2*t+1];
                }

            // loop over hidden chunks of 64 (rotated order per warp-group)
            #pragma unroll 1
            for (int hc = 0; hc < 4; hc++) {
                const int ci = (hc + rot) & 3;
                float d1c[64];              // [rs*32 + 8*ngl + q], init = b1 chunk
                #pragma unroll
                for (int ngl = 0; ngl < 4; ngl++) {
                    int tb = 8 * ci + 2 * ngl;   // n8-tile index
                    float2 bA = b1p[4*tb + tig];
                    float2 bB = b1p[4*tb + 4 + tig];
                    #pragma unroll
                    for (int rs = 0; rs < 2; rs++) {
                        d1c[rs*32 + 8*ngl + 0] = bA.x; d1c[rs*32 + 8*ngl + 1] = bA.y;
                        d1c[rs*32 + 8*ngl + 2] = bA.x; d1c[rs*32 + 8*ngl + 3] = bA.y;
                        d1c[rs*32 + 8*ngl + 4] = bB.x; d1c[rs*32 + 8*ngl + 5] = bB.y;
                        d1c[rs*32 + 8*ngl + 6] = bB.x; d1c[rs*32 + 8*ngl + 7] = bB.y;
                    }
                }
                // GEMM1 chunk: reuse each B-frag for both rowsets
                #pragma unroll
                for (int ngl = 0; ngl < 4; ngl++) {
                    #pragma unroll
                    for (int kk = 0; kk < 4; kk++) {
                        uint32_t bb[4];
                        ldsm4(bb, w1base + (uint32_t)(4*ci + ngl) * 2304 + kk * 32);
                        mma16816(d1c + 8*ngl,          a1 + 4*kk,      bb[0], bb[1]);
                        mma16816(d1c + 8*ngl + 4,      a1 + 4*kk,      bb[2], bb[3]);
                        mma16816(d1c + 32 + 8*ngl,     a1 + 16 + 4*kk, bb[0], bb[1]);
                        mma16816(d1c + 32 + 8*ngl + 4, a1 + 16 + 4*kk, bb[2], bb[3]);
                    }
                }
                // ELU -> fp16 A-frags of GEMM2 (chunk-local k64)
                uint32_t a2c[32];
                #pragma unroll
                for (int rs = 0; rs < 2; rs++)
                    #pragma unroll
                    for (int p = 0; p < 16; p++)
                        a2c[rs*16 + p] = elu2(d1c[rs*32 + 2*p], d1c[rs*32 + 2*p + 1]);
                // GEMM2 partial over this k64 chunk
                #pragma unroll
                for (int ng2 = 0; ng2 < 4; ng2++) {
                    #pragma unroll
                    for (int kk2 = 0; kk2 < 4; kk2++) {
                        uint32_t bb[4];
                        ldsm4(bb, w2base + (uint32_t)ng2 * 8448 + (uint32_t)(4*ci + kk2) * 32);
                        mma16816(d2 + 8*ng2,          a2c + 4*kk2,      bb[0], bb[1]);
                        mma16816(d2 + 8*ng2 + 4,      a2c + 4*kk2,      bb[2], bb[3]);
                        mma16816(d2 + 32 + 8*ng2,     a2c + 16 + 4*kk2, bb[0], bb[1]);
                        mma16816(d2 + 32 + 8*ng2 + 4, a2c + 16 + 4*kk2, bb[2], bb[3]);
                    }
                }
            }

            // ---- RK4 stage update ----
            const __half2 wh = __float2half2_rn((s == 1 || s == 2) ? 2.0f : 1.0f);
            #pragma unroll
            for (int i = 0; i < 32; i++) {
                __half2 pk = __floats2half2_rn(d2[2*i], d2[2*i+1]);
                acc[i] = __hfma2(pk, wh, acc[i]);
            }
            float yl[64];
            #pragma unroll
            for (int q = 0; q < 16; q++) {
                float4 v = reinterpret_cast<const float4*>(yp)[q];
                yl[4*q] = v.x; yl[4*q+1] = v.y; yl[4*q+2] = v.z; yl[4*q+3] = v.w;
            }
            if (s < 3) {
                const float cn = (s < 2) ? hdt : dt;
                #pragma unroll
                for (int rs = 0; rs < 2; rs++)
                    #pragma unroll
                    for (int j = 0; j < 16; j++)
                        a1[rs*16 + j] = pack_h2(yl[rs*32 + 2*j]     + cn * d2[rs*32 + 2*j],
                                                yl[rs*32 + 2*j + 1] + cn * d2[rs*32 + 2*j + 1]);
            } else {
                #pragma unroll
                for (int i = 0; i < 32; i++) {
                    float2 af = __half22float2(acc[i]);
                    yl[2*i]     += dt6 * af.x;
                    yl[2*i + 1] += dt6 * af.y;
                }
                #pragma unroll
                for (int q = 0; q < 16; q++)
                    reinterpret_cast<float4*>(yp)[q] =
                        make_float4(yl[4*q], yl[4*q+1], yl[4*q+2], yl[4*q+3]);
                #pragma unroll
                for (int rs = 0; rs < 2; rs++)
                    #pragma unroll
                    for (int j = 0; j < 16; j++)
                        a1[rs*16 + j] = pack_h2(yl[rs*32 + 2*j], yl[rs*32 + 2*j + 1]);
            }
        }
    }

    // ---- output ----
    {
        float yl[64];
        #pragma unroll
        for (int q = 0; q < 16; q++) {
            float4 v = reinterpret_cast<const float4*>(yp)[q];
            yl[4*q] = v.x; yl[4*q+1] = v.y; yl[4*q+2] = v.z; yl[4*q+3] = v.w;
        }
        #pragma unroll
        for (int rs = 0; rs < 2; rs++)
            #pragma unroll
            for (int h = 0; h < 2; h++) {
                float2* dst = reinterpret_cast<float2*>(
                    out + (size_t)(rowbase + rs * 16 + h * 8) * 64);
                #pragma unroll
                for (int t = 0; t < 8; t++)
                    dst[4 * t + tig] = make_float2(yl[rs*32 + 4*t + 2*h],
                                                   yl[rs*32 + 4*t + 2*h + 1]);
            }
    }
}

extern "C" void kernel_launch(void* const* d_in, const int* in_sizes, int n_in,
                              void* d_out, int out_size) {
    const float* x  = (const float*)d_in[0];
    const float* t  = (const float*)d_in[1];
    const float* W1 = (const float*)d_in[2];
    const float* b1 = (const float*)d_in[3];
    const float* W2 = (const float*)d_in[4];
    const float* b2 = (const float*)d_in[5];
    float* out = (float*)d_out;

    cudaFuncSetAttribute(node_rk4_kernel,
                         cudaFuncAttributeMaxDynamicSharedMemorySize, SMEM_BYTES);
    node_rk4_kernel<<<NTILES, NTHREADS, SMEM_BYTES>>>(x, t, W1, b1, W2, b2, out);
}

// round 6
// speedup vs baseline: 1.0811x; 1.0310x over previous
#include <cuda_runtime.h>
#include <cuda_fp16.h>
#include <cstdint>

#define NSTEPS   64
#define NTHREADS 256
#define NTILES   1024            // 262144 rows / 256 per CTA (M=32 per warp)

// SMEM: W1 [256n][64k] half, rows padded to 144B; W2 [64n][256k] half, rows 528B
//       b1 pair table (h2, [tig][tile]) 512B; y state: per-thread 64 f32, 272B pitch
#define OFF_W1 0u                // 36864
#define OFF_W2 36864u            // 33792
#define OFF_B1 70656u            // 128 h2 = 512B
#define OFF_Y  71680u            // 256*272 = 69632
#define YPITCH 272u
#define SMEM_BYTES (OFF_Y + 256u * YPITCH)   // 141312

static __device__ __forceinline__ uint32_t smem_u32(const void* p) {
    uint32_t a;
    asm("{ .reg .u64 t; cvta.to.shared.u64 t, %1; cvt.u32.u64 %0, t; }" : "=r"(a) : "l"(p));
    return a;
}
static __device__ __forceinline__ void ldsm4(uint32_t* r, uint32_t addr) {
    asm volatile("ldmatrix.sync.aligned.m8n8.x4.shared.b16 {%0,%1,%2,%3}, [%4];"
                 : "=r"(r[0]), "=r"(r[1]), "=r"(r[2]), "=r"(r[3]) : "r"(addr));
}
// f32-accum MMA (GEMM2)
static __device__ __forceinline__ void mma16816(float* d, const uint32_t* a,
                                                uint32_t b0, uint32_t b1) {
    asm volatile(
        "mma.sync.aligned.m16n8k16.row.col.f32.f16.f16.f32 "
        "{%0,%1,%2,%3}, {%4,%5,%6,%7}, {%8,%9}, {%0,%1,%2,%3};"
        : "+f"(d[0]), "+f"(d[1]), "+f"(d[2]), "+f"(d[3])
        : "r"(a[0]), "r"(a[1]), "r"(a[2]), "r"(a[3]), "r"(b0), "r"(b1));
}
// f16-accum MMA (GEMM1): D/C packed half2, 2 regs
static __device__ __forceinline__ void mma16816h(uint32_t* d, const uint32_t* a,
                                                 uint32_t b0, uint32_t b1) {
    asm volatile(
        "mma.sync.aligned.m16n8k16.row.col.f16.f16.f16.f16 "
        "{%0,%1}, {%2,%3,%4,%5}, {%6,%7}, {%0,%1};"
        : "+r"(d[0]), "+r"(d[1])
        : "r"(a[0]), "r"(a[1]), "r"(a[2]), "r"(a[3]), "r"(b0), "r"(b1));
}
static __device__ __forceinline__ uint32_t pack_h2(float a, float b) {
    __half2 h = __floats2half2_rn(a, b);
    return *reinterpret_cast<const uint32_t*>(&h);
}
static __device__ __forceinline__ __half2 exp2h2(__half2 v) {
    uint32_t r, x = *reinterpret_cast<const uint32_t*>(&v);
    asm("ex2.approx.f16x2 %0, %1;" : "=r"(r) : "r"(x));
    return *reinterpret_cast<const __half2*>(&r);
}
// branchless h2 ELU on packed half2 bits: max(x,0) + (exp(min(x,0)) - 1)
static __device__ __forceinline__ uint32_t elu_h2(uint32_t hu) {
    const __half2 z    = __float2half2_rn(0.0f);
    const __half2 l2e  = __float2half2_rn(1.44269504f);
    const __half2 one  = __float2half2_rn(1.0f);
    __half2 h  = *reinterpret_cast<const __half2*>(&hu);
    __half2 mn = __hmin2(h, z);
    __half2 mx = __hmax2(h, z);
    __half2 e  = exp2h2(__hmul2(mn, l2e));
    __half2 r  = __hadd2(mx, __hsub2(e, one));
    return *reinterpret_cast<const uint32_t*>(&r);
}

__global__ void __launch_bounds__(NTHREADS, 1)
node_rk4_kernel(const float* __restrict__ x, const float* __restrict__ tptr,
                const float* __restrict__ W1, const float* __restrict__ b1,
                const float* __restrict__ W2, const float* __restrict__ b2,
                float* __restrict__ out)
{
    extern __shared__ char base[];
    const int tid = threadIdx.x;
    const int wid = tid >> 5;
    const int lid = tid & 31;
    const int g   = lid >> 2;
    const int tig = lid & 3;

    // ---- stage weights (fp16, padded rows) + b1 pair table ----
    for (int i = tid; i < 256 * 64; i += NTHREADS) {
        int n = i >> 6, k = i & 63;
        *reinterpret_cast<__half*>(base + OFF_W1 + n * 144 + k * 2) = __float2half_rn(W1[i]);
    }
    for (int i = tid; i < 64 * 256; i += NTHREADS) {
        int n = i >> 8, k = i & 255;
        *reinterpret_cast<__half*>(base + OFF_W2 + n * 528 + k * 2) = __float2half_rn(W2[i]);
    }
    // b1 as half2 pairs: entry [tg*32 + t] = (b1[8t+2tg], b1[8t+2tg+1])
    for (int i = tid; i < 128; i += NTHREADS) {
        int t = i >> 2, tg = i & 3;
        *reinterpret_cast<uint32_t*>(base + OFF_B1 + (uint32_t)(tg * 32 + t) * 4) =
            pack_h2(b1[8*t + 2*tg], b1[8*t + 2*tg + 1]);
    }

    const uint32_t sb = smem_u32(base);
    const uint32_t lr = lid & 7, lh = (lid >> 3) & 1, ln = (lid >> 4) & 1;
    const uint32_t w1base = sb + OFF_W1 + (lr + 8 * ln) * 144 + lh * 16;
    const uint32_t w2base = sb + OFF_W2 + (lr + 8 * ln) * 528 + lh * 16;
    float* yp = reinterpret_cast<float*>(base + OFF_Y + (uint32_t)tid * YPITCH);

    float b2f[16];
    #pragma unroll
    for (int t = 0; t < 8; t++) {
        float2 v = *reinterpret_cast<const float2*>(b2 + 8 * t + tig * 2);
        b2f[2*t] = v.x; b2f[2*t+1] = v.y;
    }

    const float t0f = tptr[0];
    const float dt  = t0f * (1.0f / (float)NSTEPS);
    const float dt6 = dt * (1.0f / 6.0f);
    const float hdt = 0.5f * dt;
    const int   rot = ((wid >> 2) & 1) * 2;   // SMSP phase stagger (harmless)

    // ---- initial y: gather C-layout slices from global x ----
    const int rowbase = blockIdx.x * 256 + wid * 32 + g;
    uint32_t a1[32];                      // A-frags of GEMM1, 2 rowsets x 16
    {
        float yl[64];
        #pragma unroll
        for (int rs = 0; rs < 2; rs++)
            #pragma unroll
            for (int h = 0; h < 2; h++) {
                const float2* src = reinterpret_cast<const float2*>(
                    x + (size_t)(rowbase + rs * 16 + h * 8) * 64);
                #pragma unroll
                for (int t = 0; t < 8; t++) {
                    float2 v = src[4 * t + tig];
                    yl[rs*32 + 4*t + 2*h]     = v.x;
                    yl[rs*32 + 4*t + 2*h + 1] = v.y;
                }
            }
        #pragma unroll
        for (int q = 0; q < 16; q++)
            reinterpret_cast<float4*>(yp)[q] =
                make_float4(yl[4*q], yl[4*q+1], yl[4*q+2], yl[4*q+3]);
        #pragma unroll
        for (int rs = 0; rs < 2; rs++)
            #pragma unroll
            for (int j = 0; j < 16; j++)
                a1[rs*16 + j] = pack_h2(yl[rs*32 + 2*j], yl[rs*32 + 2*j + 1]);
    }
    __syncthreads();

    // ---- main ODE loop ----
    #pragma unroll 1
    for (int step = 0; step < NSTEPS; ++step) {
        __half2 acc[32];                    // RK4 accumulator (fp16x2)
        #pragma unroll
        for (int i = 0; i < 32; i++) acc[i] = __float2half2_rn(0.0f);

        #pragma unroll 1
        for (int s = 0; s < 4; s++) {
            // D2 accumulators (both rowsets), init = b2
            float d2[64];
            #pragma unroll
            for (int rs = 0; rs < 2; rs++)
                #pragma unroll
                for (int t = 0; t < 8; t++) {
                    d2[rs*32 + 4*t + 0] = b2f[2*t];
                    d2[rs*32 + 4*t + 1] = b2f[2*t+1];
                    d2[rs*32 + 4*t + 2] = b2f[2*t];
                    d2[rs*32 + 4*t + 3] = b2f[2*t+1];
                }

            // hidden chunks of 64 (rotated order per warp-group)
            #pragma unroll 1
            for (int hc = 0; hc < 4; hc++) {
                const int ci = (hc + rot) & 3;

                // d1h init = b1 pairs of this chunk (f16 accumulators, packed h2)
                // layout: d1h[rs*16 + 2*lt + r], lt = local tile 0..7, r = row g / g+8
                uint32_t d1h[32];
                {
                    const uint32_t boff = sb + OFF_B1 + (uint32_t)(tig * 32 + 8 * ci) * 4;
                    uint4 pA, pB;
                    asm volatile("ld.shared.v4.u32 {%0,%1,%2,%3}, [%4];"
                                 : "=r"(pA.x), "=r"(pA.y), "=r"(pA.z), "=r"(pA.w) : "r"(boff));
                    asm volatile("ld.shared.v4.u32 {%0,%1,%2,%3}, [%4];"
                                 : "=r"(pB.x), "=r"(pB.y), "=r"(pB.z), "=r"(pB.w) : "r"(boff + 16));
                    uint32_t pv[8] = {pA.x, pA.y, pA.z, pA.w, pB.x, pB.y, pB.z, pB.w};
                    #pragma unroll
                    for (int rs = 0; rs < 2; rs++)
                        #pragma unroll
                        for (int lt = 0; lt < 8; lt++) {
                            d1h[rs*16 + 2*lt + 0] = pv[lt];
                            d1h[rs*16 + 2*lt + 1] = pv[lt];
                        }
                }

                // GEMM1 chunk (f16 accum): reuse each B-frag for both rowsets
                #pragma unroll
                for (int ngl = 0; ngl < 4; ngl++) {
                    #pragma unroll
                    for (int kk = 0; kk < 4; kk++) {
                        uint32_t bb[4];
                        ldsm4(bb, w1base + (uint32_t)(4*ci + ngl) * 2304 + kk * 32);
                        mma16816h(d1h + 4*ngl,      a1 + 4*kk,      bb[0], bb[1]);
                        mma16816h(d1h + 4*ngl + 2,  a1 + 4*kk,      bb[2], bb[3]);
                        mma16816h(d1h + 16 + 4*ngl,     a1 + 16 + 4*kk, bb[0], bb[1]);
                        mma16816h(d1h + 16 + 4*ngl + 2, a1 + 16 + 4*kk, bb[2], bb[3]);
                    }
                }

                // ELU: elementwise h2 -> GEMM2 A-frags (already in frag layout)
                uint32_t a2c[32];
                #pragma unroll
                for (int i = 0; i < 32; i++) a2c[i] = elu_h2(d1h[i]);

                // GEMM2 partial over this k64 chunk (f32 accum)
                #pragma unroll
                for (int ng2 = 0; ng2 < 4; ng2++) {
                    #pragma unroll
                    for (int kk2 = 0; kk2 < 4; kk2++) {
                        uint32_t bb[4];
                        ldsm4(bb, w2base + (uint32_t)ng2 * 8448 + (uint32_t)(4*ci + kk2) * 32);
                        mma16816(d2 + 8*ng2,          a2c + 4*kk2,      bb[0], bb[1]);
                        mma16816(d2 + 8*ng2 + 4,      a2c + 4*kk2,      bb[2], bb[3]);
                        mma16816(d2 + 32 + 8*ng2,     a2c + 16 + 4*kk2, bb[0], bb[1]);
                        mma16816(d2 + 32 + 8*ng2 + 4, a2c + 16 + 4*kk2, bb[2], bb[3]);
                    }
                }
            }

            // ---- RK4 stage update ----
            const __half2 wh = __float2half2_rn((s == 1 || s == 2) ? 2.0f : 1.0f);
            #pragma unroll
            for (int i = 0; i < 32; i++) {
                __half2 pk = __floats2half2_rn(d2[2*i], d2[2*i+1]);
                acc[i] = __hfma2(pk, wh, acc[i]);
            }
            float yl[64];
            #pragma unroll
            for (int q = 0; q < 16; q++) {
                float4 v = reinterpret_cast<const float4*>(yp)[q];
                yl[4*q] = v.x; yl[4*q+1] = v.y; yl[4*q+2] = v.z; yl[4*q+3] = v.w;
            }
            if (s < 3) {
                const float cn = (s < 2) ? hdt : dt;
                #pragma unroll
                for (int rs = 0; rs < 2; rs++)
                    #pragma unroll
                    for (int j = 0; j < 16; j++)
                        a1[rs*16 + j] = pack_h2(yl[rs*32 + 2*j]     + cn * d2[rs*32 + 2*j],
                                                yl[rs*32 + 2*j + 1] + cn * d2[rs*32 + 2*j + 1]);
            } else {
                #pragma unroll
                for (int i = 0; i < 32; i++) {
                    float2 af = __half22float2(acc[i]);
                    yl[2*i]     += dt6 * af.x;
                    yl[2*i + 1] += dt6 * af.y;
                }
                #pragma unroll
                for (int q = 0; q < 16; q++)
                    reinterpret_cast<float4*>(yp)[q] =
                        make_float4(yl[4*q], yl[4*q+1], yl[4*q+2], yl[4*q+3]);
                #pragma unroll
                for (int rs = 0; rs < 2; rs++)
                    #pragma unroll
                    for (int j = 0; j < 16; j++)
                        a1[rs*16 + j] = pack_h2(yl[rs*32 + 2*j], yl[rs*32 + 2*j + 1]);
            }
        }
    }

    // ---- output ----
    {
        float yl[64];
        #pragma unroll
        for (int q = 0; q < 16; q++) {
            float4 v = reinterpret_cast<const float4*>(yp)[q];
            yl[4*q] = v.x; yl[4*q+1] = v.y; yl[4*q+2] = v.z; yl[4*q+3] = v.w;
        }
        #pragma unroll
        for (int rs = 0; rs < 2; rs++)
            #pragma unroll
            for (int h = 0; h < 2; h++) {
                float2* dst = reinterpret_cast<float2*>(
                    out + (size_t)(rowbase + rs * 16 + h * 8) * 64);
                #pragma unroll
                for (int t = 0; t < 8; t++)
                    dst[4 * t + tig] = make_float2(yl[rs*32 + 4*t + 2*h],
                                                   yl[rs*32 + 4*t + 2*h + 1]);
            }
    }
}

extern "C" void kernel_launch(void* const* d_in, const int* in_sizes, int n_in,
                              void* d_out, int out_size) {
    const float* x  = (const float*)d_in[0];
    const float* t  = (const float*)d_in[1];
    const float* W1 = (const float*)d_in[2];
    const float* b1 = (const float*)d_in[3];
    const float* W2 = (const float*)d_in[4];
    const float* b2 = (const float*)d_in[5];
    float* out = (float*)d_out;

    cudaFuncSetAttribute(node_rk4_kernel,
                         cudaFuncAttributeMaxDynamicSharedMemorySize, SMEM_BYTES);
    node_rk4_kernel<<<NTILES, NTHREADS, SMEM_BYTES>>>(x, t, W1, b1, W2, b2, out);
}

// round 7
// speedup vs baseline: 1.1166x; 1.0329x over previous
#include <cuda_runtime.h>
#include <cuda_fp16.h>
#include <cstdint>

#define NSTEPS   64
#define NTHREADS 256
#define NTILES   1024            // 262144 rows / 256 per CTA (M=32 per warp)

// SMEM: W1 [256n][64k] half, rows padded to 144B; W2 [64n][256k] half, rows 528B
//       b1 pair table (h2) 512B; y state: per-thread 64 f32, 272B pitch
#define OFF_W1 0u                // 36864
#define OFF_W2 36864u            // 33792
#define OFF_B1 70656u            // 128 h2 = 512B
#define OFF_Y  71680u            // 256*272 = 69632
#define YPITCH 272u
#define SMEM_BYTES (OFF_Y + 256u * YPITCH)   // 141312

static __device__ __forceinline__ uint32_t smem_u32(const void* p) {
    uint32_t a;
    asm("{ .reg .u64 t; cvta.to.shared.u64 t, %1; cvt.u32.u64 %0, t; }" : "=r"(a) : "l"(p));
    return a;
}
static __device__ __forceinline__ void ldsm4(uint32_t* r, uint32_t addr) {
    asm volatile("ldmatrix.sync.aligned.m8n8.x4.shared.b16 {%0,%1,%2,%3}, [%4];"
                 : "=r"(r[0]), "=r"(r[1]), "=r"(r[2]), "=r"(r[3]) : "r"(addr));
}
// f16-accum MMA: D/C packed half2, 2 regs
static __device__ __forceinline__ void mma16816h(uint32_t* d, const uint32_t* a,
                                                 uint32_t b0, uint32_t b1) {
    asm volatile(
        "mma.sync.aligned.m16n8k16.row.col.f16.f16.f16.f16 "
        "{%0,%1}, {%2,%3,%4,%5}, {%6,%7}, {%0,%1};"
        : "+r"(d[0]), "+r"(d[1])
        : "r"(a[0]), "r"(a[1]), "r"(a[2]), "r"(a[3]), "r"(b0), "r"(b1));
}
static __device__ __forceinline__ uint32_t pack_h2(float a, float b) {
    __half2 h = __floats2half2_rn(a, b);
    return *reinterpret_cast<const uint32_t*>(&h);
}
static __device__ __forceinline__ __half2 exp2h2(__half2 v) {
    uint32_t r, x = *reinterpret_cast<const uint32_t*>(&v);
    asm("ex2.approx.f16x2 %0, %1;" : "=r"(r) : "r"(x));
    return *reinterpret_cast<const __half2*>(&r);
}
// branchless h2 ELU on packed bits: max(x,0) + (exp(min(x,0)) - 1)
static __device__ __forceinline__ uint32_t elu_h2(uint32_t hu) {
    const __half2 z    = __float2half2_rn(0.0f);
    const __half2 l2e  = __float2half2_rn(1.44269504f);
    const __half2 one  = __float2half2_rn(1.0f);
    __half2 h  = *reinterpret_cast<const __half2*>(&hu);
    __half2 mn = __hmin2(h, z);
    __half2 mx = __hmax2(h, z);
    __half2 e  = exp2h2(__hmul2(mn, l2e));
    __half2 r  = __hadd2(mx, __hsub2(e, one));
    return *reinterpret_cast<const uint32_t*>(&r);
}
static __device__ __forceinline__ uint32_t hfma2_u(uint32_t a, __half2 b, uint32_t c) {
    __half2 r = __hfma2(*reinterpret_cast<const __half2*>(&a), b,
                        *reinterpret_cast<const __half2*>(&c));
    return *reinterpret_cast<const uint32_t*>(&r);
}

__global__ void __launch_bounds__(NTHREADS, 1)
node_rk4_kernel(const float* __restrict__ x, const float* __restrict__ tptr,
                const float* __restrict__ W1, const float* __restrict__ b1,
                const float* __restrict__ W2, const float* __restrict__ b2,
                float* __restrict__ out)
{
    extern __shared__ char base[];
    const int tid = threadIdx.x;
    const int wid = tid >> 5;
    const int lid = tid & 31;
    const int g   = lid >> 2;
    const int tig = lid & 3;

    // ---- stage weights (fp16, padded rows) + b1 pair table ----
    for (int i = tid; i < 256 * 64; i += NTHREADS) {
        int n = i >> 6, k = i & 63;
        *reinterpret_cast<__half*>(base + OFF_W1 + n * 144 + k * 2) = __float2half_rn(W1[i]);
    }
    for (int i = tid; i < 64 * 256; i += NTHREADS) {
        int n = i >> 8, k = i & 255;
        *reinterpret_cast<__half*>(base + OFF_W2 + n * 528 + k * 2) = __float2half_rn(W2[i]);
    }
    for (int i = tid; i < 128; i += NTHREADS) {
        int t = i >> 2, tg = i & 3;
        *reinterpret_cast<uint32_t*>(base + OFF_B1 + (uint32_t)(tg * 32 + t) * 4) =
            pack_h2(b1[8*t + 2*tg], b1[8*t + 2*tg + 1]);
    }

    const uint32_t sb = smem_u32(base);
    const uint32_t lr = lid & 7, lh = (lid >> 3) & 1, ln = (lid >> 4) & 1;
    const uint32_t w1base = sb + OFF_W1 + (lr + 8 * ln) * 144 + lh * 16;
    const uint32_t w2base = sb + OFF_W2 + (lr + 8 * ln) * 528 + lh * 16;
    float* yp = reinterpret_cast<float*>(base + OFF_Y + (uint32_t)tid * YPITCH);

    // b2 as h2 pairs for this thread's columns, tile t=0..7
    uint32_t b2h[8];
    #pragma unroll
    for (int t = 0; t < 8; t++) {
        float2 v = *reinterpret_cast<const float2*>(b2 + 8 * t + tig * 2);
        b2h[t] = pack_h2(v.x, v.y);
    }

    const float t0f = tptr[0];
    const float dt  = t0f * (1.0f / (float)NSTEPS);
    const float dt6 = dt * (1.0f / 6.0f);
    const float hdt = 0.5f * dt;
    const __half2 one_h  = __float2half2_rn(1.0f);
    const __half2 two_h  = __float2half2_rn(2.0f);
    const __half2 hdt_h  = __float2half2_rn(hdt);
    const __half2 dt_h   = __float2half2_rn(dt);
    const int rot = ((wid >> 2) & 1) * 2;   // SMSP phase stagger

    // ---- initial y: gather C-layout slices from global x ----
    const int rowbase = blockIdx.x * 256 + wid * 32 + g;
    uint32_t a1[32];   // GEMM1 A-frags (current stage input), h2
    uint32_t yh[32];   // h2 snapshot of y (stage-0 input), persists across stages
    {
        float yl[64];
        #pragma unroll
        for (int rs = 0; rs < 2; rs++)
            #pragma unroll
            for (int h = 0; h < 2; h++) {
                const float2* src = reinterpret_cast<const float2*>(
                    x + (size_t)(rowbase + rs * 16 + h * 8) * 64);
                #pragma unroll
                for (int t = 0; t < 8; t++) {
                    float2 v = src[4 * t + tig];
                    yl[rs*32 + 4*t + 2*h]     = v.x;
                    yl[rs*32 + 4*t + 2*h + 1] = v.y;
                }
            }
        #pragma unroll
        for (int q = 0; q < 16; q++)
            reinterpret_cast<float4*>(yp)[q] =
                make_float4(yl[4*q], yl[4*q+1], yl[4*q+2], yl[4*q+3]);
        #pragma unroll
        for (int i = 0; i < 32; i++) {
            a1[i] = pack_h2(yl[2*i], yl[2*i+1]);
            yh[i] = a1[i];
        }
    }
    __syncthreads();

    // ---- main ODE loop ----
    #pragma unroll 1
    for (int step = 0; step < NSTEPS; ++step) {
        uint32_t acc[32];                    // RK4 accumulator (h2)
        #pragma unroll
        for (int i = 0; i < 32; i++) acc[i] = 0u;

        #pragma unroll 1
        for (int s = 0; s < 4; s++) {
            // D2 accumulators (h2), init = b2:  d2h[rs*16 + 2t + r]
            uint32_t d2h[32];
            #pragma unroll
            for (int rs = 0; rs < 2; rs++)
                #pragma unroll
                for (int t = 0; t < 8; t++) {
                    d2h[rs*16 + 2*t + 0] = b2h[t];
                    d2h[rs*16 + 2*t + 1] = b2h[t];
                }

            // hidden chunks of 64 (rotated order per warp-group)
            #pragma unroll 1
            for (int hc = 0; hc < 4; hc++) {
                const int ci = (hc + rot) & 3;

                // prefetch first GEMM1 B-tile of this chunk
                uint32_t bbX[4], bbY[4];
                ldsm4(bbX, w1base + (uint32_t)(4*ci) * 2304);

                // d1h init = b1 pairs of this chunk (h2 accumulators)
                uint32_t d1h[32];
                {
                    const uint32_t boff = sb + OFF_B1 + (uint32_t)(tig * 32 + 8 * ci) * 4;
                    uint4 pA, pB;
                    asm volatile("ld.shared.v4.u32 {%0,%1,%2,%3}, [%4];"
                                 : "=r"(pA.x), "=r"(pA.y), "=r"(pA.z), "=r"(pA.w) : "r"(boff));
                    asm volatile("ld.shared.v4.u32 {%0,%1,%2,%3}, [%4];"
                                 : "=r"(pB.x), "=r"(pB.y), "=r"(pB.z), "=r"(pB.w) : "r"(boff + 16));
                    uint32_t pv[8] = {pA.x, pA.y, pA.z, pA.w, pB.x, pB.y, pB.z, pB.w};
                    #pragma unroll
                    for (int rs = 0; rs < 2; rs++)
                        #pragma unroll
                        for (int lt = 0; lt < 8; lt++) {
                            d1h[rs*16 + 2*lt + 0] = pv[lt];
                            d1h[rs*16 + 2*lt + 1] = pv[lt];
                        }
                }

                // GEMM1 chunk (f16 accum), ldsm double-buffered
                #pragma unroll
                for (int j = 0; j < 16; j++) {
                    const int ngl = j >> 2, kk = j & 3;
                    uint32_t* cur = (j & 1) ? bbY : bbX;
                    uint32_t* nxt = (j & 1) ? bbX : bbY;
                    if (j < 15) {
                        const int jn = j + 1;
                        ldsm4(nxt, w1base + (uint32_t)(4*ci + (jn >> 2)) * 2304 + (jn & 3) * 32);
                    }
                    mma16816h(d1h + 4*ngl,          a1 + 4*kk,      cur[0], cur[1]);
                    mma16816h(d1h + 4*ngl + 2,      a1 + 4*kk,      cur[2], cur[3]);
                    mma16816h(d1h + 16 + 4*ngl,     a1 + 16 + 4*kk, cur[0], cur[1]);
                    mma16816h(d1h + 16 + 4*ngl + 2, a1 + 16 + 4*kk, cur[2], cur[3]);
                }

                // prefetch first GEMM2 B-tile BEFORE the ELU block
                uint32_t cbX[4], cbY[4];
                ldsm4(cbX, w2base + (uint32_t)(4*ci) * 32);

                // ELU: elementwise h2 (output already in GEMM2 A-frag layout)
                uint32_t a2c[32];
                #pragma unroll
                for (int i = 0; i < 32; i++) a2c[i] = elu_h2(d1h[i]);

                // GEMM2 partial over this k64 chunk (f16 accum), double-buffered
                #pragma unroll
                for (int j = 0; j < 16; j++) {
                    const int ng2 = j >> 2, kk2 = j & 3;
                    uint32_t* cur = (j & 1) ? cbY : cbX;
                    uint32_t* nxt = (j & 1) ? cbX : cbY;
                    if (j < 15) {
                        const int jn = j + 1;
                        ldsm4(nxt, w2base + (uint32_t)(jn >> 2) * 8448
                                          + (uint32_t)(4*ci + (jn & 3)) * 32);
                    }
                    mma16816h(d2h + 4*ng2,          a2c + 4*kk2,      cur[0], cur[1]);
                    mma16816h(d2h + 4*ng2 + 2,      a2c + 4*kk2,      cur[2], cur[3]);
                    mma16816h(d2h + 16 + 4*ng2,     a2c + 16 + 4*kk2, cur[0], cur[1]);
                    mma16816h(d2h + 16 + 4*ng2 + 2, a2c + 16 + 4*kk2, cur[2], cur[3]);
                }
            }

            // ---- RK4 stage update (all h2) ----
            const __half2 wh = (s == 1 || s == 2) ? two_h : one_h;
            #pragma unroll
            for (int i = 0; i < 32; i++) acc[i] = hfma2_u(d2h[i], wh, acc[i]);

            if (s < 3) {
                const __half2 cnh = (s < 2) ? hdt_h : dt_h;
                #pragma unroll
                for (int i = 0; i < 32; i++) a1[i] = hfma2_u(d2h[i], cnh, yh[i]);
            } else {
                float yl[64];
                #pragma unroll
                for (int q = 0; q < 16; q++) {
                    float4 v = reinterpret_cast<const float4*>(yp)[q];
                    yl[4*q] = v.x; yl[4*q+1] = v.y; yl[4*q+2] = v.z; yl[4*q+3] = v.w;
                }
                #pragma unroll
                for (int i = 0; i < 32; i++) {
                    float2 af = __half22float2(*reinterpret_cast<const __half2*>(&acc[i]));
                    yl[2*i]     += dt6 * af.x;
                    yl[2*i + 1] += dt6 * af.y;
                }
                #pragma unroll
                for (int q = 0; q < 16; q++)
                    reinterpret_cast<float4*>(yp)[q] =
                        make_float4(yl[4*q], yl[4*q+1], yl[4*q+2], yl[4*q+3]);
                #pragma unroll
                for (int i = 0; i < 32; i++) {
                    a1[i] = pack_h2(yl[2*i], yl[2*i+1]);
                    yh[i] = a1[i];
                }
            }
        }
    }

    // ---- output ----
    {
        float yl[64];
        #pragma unroll
        for (int q = 0; q < 16; q++) {
            float4 v = reinterpret_cast<const float4*>(yp)[q];
            yl[4*q] = v.x; yl[4*q+1] = v.y; yl[4*q+2] = v.z; yl[4*q+3] = v.w;
        }
        #pragma unroll
        for (int rs = 0; rs < 2; rs++)
            #pragma unroll
            for (int h = 0; h < 2; h++) {
                float2* dst = reinterpret_cast<float2*>(
                    out + (size_t)(rowbase + rs * 16 + h * 8) * 64);
                #pragma unroll
                for (int t = 0; t < 8; t++)
                    dst[4 * t + tig] = make_float2(yl[rs*32 + 4*t + 2*h],
                                                   yl[rs*32 + 4*t + 2*h + 1]);
            }
    }
}

extern "C" void kernel_launch(void* const* d_in, const int* in_sizes, int n_in,
                              void* d_out, int out_size) {
    const float* x  = (const float*)d_in[0];
    const float* t  = (const float*)d_in[1];
    const float* W1 = (const float*)d_in[2];
    const float* b1 = (const float*)d_in[3];
    const float* W2 = (const float*)d_in[4];
    const float* b2 = (const float*)d_in[5];
    float* out = (float*)d_out;

    cudaFuncSetAttribute(node_rk4_kernel,
                         cudaFuncAttributeMaxDynamicSharedMemorySize, SMEM_BYTES);
    node_rk4_kernel<<<NTILES, NTHREADS, SMEM_BYTES>>>(x, t, W1, b1, W2, b2, out);
}